// round 15
// baseline (speedup 1.0000x reference)
#include <cuda_runtime.h>
#include <cuda_bf16.h>
#include <stdint.h>

typedef __nv_bfloat16 bf16;

// Problem dims (fixed)
#define B_ 2
#define D_ 4096
#define S_ 2048
#define F_ 16384

// ---------------------------------------------------------------------------
// Scratch (device globals; allocation-free per harness rules)
// ---------------------------------------------------------------------------
__device__ bf16  g_xThi[(size_t)B_ * S_ * D_];   // x^T per batch [S, D]
__device__ bf16  g_xTlo[(size_t)B_ * S_ * D_];
__device__ bf16  g_w0hi[(size_t)F_ * D_];
__device__ bf16  g_w0lo[(size_t)F_ * D_];
__device__ bf16  g_w1hi[(size_t)F_ * D_];
__device__ bf16  g_w1lo[(size_t)F_ * D_];
__device__ bf16  g_wohi[(size_t)D_ * F_];
__device__ bf16  g_wolo[(size_t)D_ * F_];
__device__ bf16  g_hhi[(size_t)B_ * S_ * F_];    // H^T  [S, F]
__device__ bf16  g_hlo[(size_t)B_ * S_ * F_];

// ---------------------------------------------------------------------------
// PTX helpers (sm_80-era only; NO tcgen05 — ptxas targets plain sm_103)
// ---------------------------------------------------------------------------
__device__ __forceinline__ void cp16(uint32_t s, const void* g) {
    asm volatile("cp.async.cg.shared.global [%0], [%1], 16;\n" :: "r"(s), "l"(g));
}

__device__ __forceinline__ void ldsm_x4(uint32_t addr, uint32_t* r) {
    asm volatile(
        "ldmatrix.sync.aligned.m8n8.x4.shared.b16 {%0,%1,%2,%3}, [%4];\n"
        : "=r"(r[0]), "=r"(r[1]), "=r"(r[2]), "=r"(r[3]) : "r"(addr));
}

__device__ __forceinline__ void mma_bf16(float* c, const uint32_t* a,
                                         uint32_t b0, uint32_t b1) {
    asm volatile(
        "mma.sync.aligned.m16n8k16.row.col.f32.bf16.bf16.f32 "
        "{%0,%1,%2,%3}, {%4,%5,%6,%7}, {%8,%9}, {%0,%1,%2,%3};\n"
        : "+f"(c[0]), "+f"(c[1]), "+f"(c[2]), "+f"(c[3])
        : "r"(a[0]), "r"(a[1]), "r"(a[2]), "r"(a[3]), "r"(b0), "r"(b1));
}

__device__ __forceinline__ float gelu_exact(float v) {
    return 0.5f * v * (1.0f + erff(v * 0.70710678118654752440f));
}

#define SWZ(x)   ((x) ^ (((x) >> 3) & 0x70))   // SW128 (128B rows)
#define SWZ64(x) ((x) ^ (((x) >> 3) & 0x30))   // SW64  (64B rows)

// ===========================================================================
// GEMM1 fused, 2 CTAs/SM: CTA tile 128(S) x 64(F) PER PRODUCT; warps 0-3
// compute gate = (xT)(w0^T), warps 4-7 compute up = (xT)(w1^T); warp tile
// 32(S) x 64(F). bf16x3, fp32 accum, terms serialized to cap registers.
// 3-stage cp.async, BK=32, SW64 (64B rows). Stage: Ah8K Al8K W0h4K W0l4K
// W1h4K W1l4K = 32K; 3 stages = 96K -> 2 CTAs resident.
// Epilogue: h = gelu(gate)*up -> bf16 hi/lo.
// ===========================================================================
constexpr int BK1 = 32;
constexpr int G1_STAGE = 32768;
constexpr int G1_NSTG  = 3;
constexpr int G1_SMEM  = G1_NSTG * G1_STAGE;     // 98304

__device__ __forceinline__ void g1_load_stage(
    uint32_t st, const bf16* __restrict__ Ah, const bf16* __restrict__ Al,
    const bf16* __restrict__ W0h, const bf16* __restrict__ W0l,
    const bf16* __restrict__ W1h, const bf16* __restrict__ W1l,
    size_t m0, size_t n0, int k0, int tid) {
    const int K = D_;
    // A: 128 rows x 64B (BK=32), hi+lo: 512 chunks each
    #pragma unroll
    for (int i = 0; i < 2; ++i) {
        int cc = tid + i * 256;           // 0..511
        int r = cc >> 2, cb = (cc & 3) * 16;
        size_t gbyte = (((m0 + r) * (size_t)K + k0) << 1) + cb;
        uint32_t s = SWZ64((uint32_t)(r * 64 + cb));
        cp16(st + s,        (const char*)Ah + gbyte);
        cp16(st + 8192 + s, (const char*)Al + gbyte);
    }
    // B: 4 subtiles (w0h,w0l,w1h,w1l), each 64 rows x 64B = 256 chunks
    #pragma unroll
    for (int sub = 0; sub < 4; ++sub) {
        int cc = tid;                     // 0..255
        int r = cc >> 2, cb = (cc & 3) * 16;
        size_t gbyte = (((n0 + r) * (size_t)K + k0) << 1) + cb;
        uint32_t s = SWZ64((uint32_t)(r * 64 + cb));
        const bf16* p = (sub == 0) ? W0h : (sub == 1) ? W0l : (sub == 2) ? W1h : W1l;
        cp16(st + 16384 + sub * 4096 + s, (const char*)p + gbyte);
    }
}

__global__ void __launch_bounds__(256, 2) gemm1_fused(
    const bf16* __restrict__ Ah, const bf16* __restrict__ Al,
    const bf16* __restrict__ W0h, const bf16* __restrict__ W0l,
    const bf16* __restrict__ W1h, const bf16* __restrict__ W1l,
    bf16* __restrict__ Hhi, bf16* __restrict__ Hlo) {
    extern __shared__ char smem[];
    uint32_t sb = (uint32_t)__cvta_generic_to_shared(smem);
    int tid = threadIdx.x, wid = tid >> 5, lane = tid & 31;
    int grp = wid >> 2;        // 0 = gate(w0), 1 = up(w1)
    int wg  = wid & 3;         // 4 warps along M, 32 rows each

    int b = blockIdx.z;
    const bf16* xh = Ah + (size_t)b * S_ * D_;
    const bf16* xl = Al + (size_t)b * S_ * D_;
    bf16* Oh = Hhi + (size_t)b * S_ * F_;
    bf16* Ol = Hlo + (size_t)b * S_ * F_;
    size_t m0 = (size_t)blockIdx.x * 128;
    size_t n0 = (size_t)blockIdx.y * 64;
    const int KT = D_ / BK1;   // 128

    float c[2][8][4];
    #pragma unroll
    for (int mi = 0; mi < 2; ++mi)
        #pragma unroll
        for (int ni = 0; ni < 8; ++ni)
            #pragma unroll
            for (int r = 0; r < 4; ++r) c[mi][ni][r] = 0.0f;

    g1_load_stage(sb,                xh, xl, W0h, W0l, W1h, W1l, m0, n0, 0,        tid);
    asm volatile("cp.async.commit_group;\n" ::: "memory");
    g1_load_stage(sb + G1_STAGE,     xh, xl, W0h, W0l, W1h, W1l, m0, n0, BK1,      tid);
    asm volatile("cp.async.commit_group;\n" ::: "memory");

    int aRow = wg * 32 + (lane & 15);
    int aCol = (lane >> 4) * 16;
    int bRow = (lane & 7) + ((lane >> 4) << 3);
    int bCol = ((lane >> 3) & 1) * 16;
    uint32_t bBase = 16384 + grp * 8192;    // this group's B (hi @+0, lo @+4096)

    for (int kt = 0; kt < KT; ++kt) {
        if (kt + 1 < KT) asm volatile("cp.async.wait_group 1;\n" ::: "memory");
        else             asm volatile("cp.async.wait_group 0;\n" ::: "memory");
        __syncthreads();   // sole barrier per stage
        uint32_t st = sb + (kt % G1_NSTG) * G1_STAGE;
        if (kt + 2 < KT) {
            g1_load_stage(sb + ((kt + 2) % G1_NSTG) * G1_STAGE, xh, xl,
                          W0h, W0l, W1h, W1l, m0, n0, (kt + 2) * BK1, tid);
            asm volatile("cp.async.commit_group;\n" ::: "memory");
        }

        #pragma unroll
        for (int ks = 0; ks < 2; ++ks) {
            uint32_t ah[2][4], al[2][4], bb[4][4];
            #pragma unroll
            for (int mi = 0; mi < 2; ++mi) {
                uint32_t off = SWZ64((uint32_t)((aRow + mi * 16) * 64 + ks * 32 + aCol));
                ldsm_x4(st + off,        ah[mi]);
                ldsm_x4(st + 8192 + off, al[mi]);
            }
            // B-hi frags
            #pragma unroll
            for (int nj = 0; nj < 4; ++nj) {
                uint32_t off = SWZ64((uint32_t)((bRow + nj * 16) * 64 + ks * 32 + bCol));
                ldsm_x4(st + bBase + off, bb[nj]);
            }
            // term 1: Ahi * Bhi
            #pragma unroll
            for (int mi = 0; mi < 2; ++mi)
                #pragma unroll
                for (int ni = 0; ni < 8; ++ni) {
                    int nj = ni >> 1, pr = (ni & 1) * 2;
                    mma_bf16(c[mi][ni], ah[mi], bb[nj][pr], bb[nj][pr + 1]);
                }
            // term 3: Alo * Bhi
            #pragma unroll
            for (int mi = 0; mi < 2; ++mi)
                #pragma unroll
                for (int ni = 0; ni < 8; ++ni) {
                    int nj = ni >> 1, pr = (ni & 1) * 2;
                    mma_bf16(c[mi][ni], al[mi], bb[nj][pr], bb[nj][pr + 1]);
                }
            // reload B-lo over bb, then term 2: Ahi * Blo
            #pragma unroll
            for (int nj = 0; nj < 4; ++nj) {
                uint32_t off = SWZ64((uint32_t)((bRow + nj * 16) * 64 + ks * 32 + bCol));
                ldsm_x4(st + bBase + 4096 + off, bb[nj]);
            }
            #pragma unroll
            for (int mi = 0; mi < 2; ++mi)
                #pragma unroll
                for (int ni = 0; ni < 8; ++ni) {
                    int nj = ni >> 1, pr = (ni & 1) * 2;
                    mma_bf16(c[mi][ni], ah[mi], bb[nj][pr], bb[nj][pr + 1]);
                }
        }
    }

    // ---- Fused epilogue: h = gelu(gate) * up, split bf16 hi/lo ----
    __syncthreads();                         // mainloop smem reads finished
    float* gsm = (float*)smem;               // 4 warps x 2048 floats = 32KB
    int slotBase = wg * 2048 + lane;         // lane-major: conflict-free
    if (grp == 0) {
        #pragma unroll
        for (int mi = 0; mi < 2; ++mi)
            #pragma unroll
            for (int ni = 0; ni < 8; ++ni)
                #pragma unroll
                for (int r = 0; r < 4; ++r)
                    gsm[slotBase + (mi * 32 + ni * 4 + r) * 32] = c[mi][ni][r];
    }
    __syncthreads();
    if (grp == 1) {
        #pragma unroll
        for (int mi = 0; mi < 2; ++mi) {
            #pragma unroll
            for (int ni = 0; ni < 8; ++ni) {
                float h[4];
                #pragma unroll
                for (int r = 0; r < 4; ++r) {
                    float gate = gsm[slotBase + (mi * 32 + ni * 4 + r) * 32];
                    h[r] = gelu_exact(gate) * c[mi][ni][r];
                }
                size_t row = m0 + wg * 32 + mi * 16 + (lane >> 2);
                size_t col = n0 + ni * 8 + (lane & 3) * 2;
                #pragma unroll
                for (int half = 0; half < 2; ++half) {
                    float v0 = h[half * 2], v1 = h[half * 2 + 1];
                    bf16 h0 = __float2bfloat16(v0), h1 = __float2bfloat16(v1);
                    __nv_bfloat162 hi2 = { h0, h1 };
                    __nv_bfloat162 lo2 = { __float2bfloat16(v0 - __bfloat162float(h0)),
                                           __float2bfloat16(v1 - __bfloat162float(h1)) };
                    size_t o = (row + half * 8) * (size_t)F_ + col;
                    *(__nv_bfloat162*)(Oh + o) = hi2;
                    *(__nv_bfloat162*)(Ol + o) = lo2;
                }
            }
        }
    }
}

// ===========================================================================
// GEMM2, 2 CTAs/SM (unchanged from R14): CTA 128(S) x 64(D), 8 warps as
// 4(M) x 2(N), warp tile 32x32. 2-stage cp.async, BK=64, SW128.
// Writes out[b][d][s] directly (transposed scatter).
// ===========================================================================
constexpr int BK = 64;
constexpr int G2_STAGE = 49152;
constexpr int G2_SMEM  = 2 * G2_STAGE;      // 98304

__device__ __forceinline__ void g2_load_stage(
    uint32_t st, const bf16* __restrict__ Ah, const bf16* __restrict__ Al,
    const bf16* __restrict__ Bh, const bf16* __restrict__ Bl,
    size_t m0, size_t n0, int k0, int K, int tid) {
    #pragma unroll
    for (int i = 0; i < 4; ++i) {
        int cc = tid + i * 256;
        int r = cc >> 3, cb = (cc & 7) * 16;
        size_t gbyte = (((m0 + r) * (size_t)K + k0) << 1) + cb;
        uint32_t s = SWZ((uint32_t)(r * 128 + cb));
        cp16(st + s,         (const char*)Ah + gbyte);
        cp16(st + 16384 + s, (const char*)Al + gbyte);
    }
    #pragma unroll
    for (int i = 0; i < 2; ++i) {
        int cc = tid + i * 256;
        int r = cc >> 3, cb = (cc & 7) * 16;
        size_t gbyte = (((n0 + r) * (size_t)K + k0) << 1) + cb;
        uint32_t s = SWZ((uint32_t)(r * 128 + cb));
        cp16(st + 32768 + s, (const char*)Bh + gbyte);
        cp16(st + 40960 + s, (const char*)Bl + gbyte);
    }
}

__global__ void __launch_bounds__(256, 2) gemm2_mma(
    const bf16* __restrict__ gAh, const bf16* __restrict__ gAl,
    const bf16* __restrict__ Bh, const bf16* __restrict__ Bl,
    float* __restrict__ gOut) {
    extern __shared__ char smem[];
    uint32_t sb = (uint32_t)__cvta_generic_to_shared(smem);
    int tid = threadIdx.x, wid = tid >> 5, lane = tid & 31;
    int wm = wid >> 1;        // 4 warps along M(S), 32 rows each
    int wn = wid & 1;         // 2 warps along N(D), 32 cols each

    int b = blockIdx.z;
    const bf16* Ah = gAh + (size_t)b * S_ * F_;
    const bf16* Al = gAl + (size_t)b * S_ * F_;
    float* Out = gOut + (size_t)b * D_ * S_;
    size_t m0 = (size_t)blockIdx.x * 128;
    size_t n0 = (size_t)blockIdx.y * 64;
    const int K = F_;
    const int KT = K / BK;    // 256

    float c[2][4][4];
    #pragma unroll
    for (int mi = 0; mi < 2; ++mi)
        #pragma unroll
        for (int ni = 0; ni < 4; ++ni)
            #pragma unroll
            for (int r = 0; r < 4; ++r) c[mi][ni][r] = 0.0f;

    g2_load_stage(sb,            Ah, Al, Bh, Bl, m0, n0, 0,  K, tid);
    asm volatile("cp.async.commit_group;\n" ::: "memory");
    g2_load_stage(sb + G2_STAGE, Ah, Al, Bh, Bl, m0, n0, BK, K, tid);
    asm volatile("cp.async.commit_group;\n" ::: "memory");

    int aRow = wm * 32 + (lane & 15);
    int aCol = (lane >> 4) * 16;
    int bRow = wn * 32 + (lane & 7) + ((lane >> 4) << 3);
    int bCol = ((lane >> 3) & 1) * 16;

    for (int kt = 0; kt < KT; ++kt) {
        if (kt + 1 < KT) asm volatile("cp.async.wait_group 1;\n" ::: "memory");
        else             asm volatile("cp.async.wait_group 0;\n" ::: "memory");
        __syncthreads();
        uint32_t st = sb + (kt & 1) * G2_STAGE;

        #pragma unroll
        for (int ks = 0; ks < 4; ++ks) {
            uint32_t ah[2][4], al[2][4], bh[2][4], bl[2][4];
            #pragma unroll
            for (int mi = 0; mi < 2; ++mi) {
                uint32_t off = SWZ((uint32_t)((aRow + mi * 16) * 128 + ks * 32 + aCol));
                ldsm_x4(st + off,         ah[mi]);
                ldsm_x4(st + 16384 + off, al[mi]);
            }
            #pragma unroll
            for (int nj = 0; nj < 2; ++nj) {
                uint32_t off = SWZ((uint32_t)((bRow + nj * 16) * 128 + ks * 32 + bCol));
                ldsm_x4(st + 32768 + off, bh[nj]);
                ldsm_x4(st + 40960 + off, bl[nj]);
            }
            #pragma unroll
            for (int mi = 0; mi < 2; ++mi)
                #pragma unroll
                for (int ni = 0; ni < 4; ++ni) {
                    int nj = ni >> 1, pr = (ni & 1) * 2;
                    mma_bf16(c[mi][ni], ah[mi], bh[nj][pr], bh[nj][pr + 1]);
                }
            #pragma unroll
            for (int mi = 0; mi < 2; ++mi)
                #pragma unroll
                for (int ni = 0; ni < 4; ++ni) {
                    int nj = ni >> 1, pr = (ni & 1) * 2;
                    mma_bf16(c[mi][ni], ah[mi], bl[nj][pr], bl[nj][pr + 1]);
                }
            #pragma unroll
            for (int mi = 0; mi < 2; ++mi)
                #pragma unroll
                for (int ni = 0; ni < 4; ++ni) {
                    int nj = ni >> 1, pr = (ni & 1) * 2;
                    mma_bf16(c[mi][ni], al[mi], bh[nj][pr], bh[nj][pr + 1]);
                }
        }
        __syncthreads();
        if (kt + 2 < KT) {
            g2_load_stage(st, Ah, Al, Bh, Bl, m0, n0, (kt + 2) * BK, K, tid);
            asm volatile("cp.async.commit_group;\n" ::: "memory");
        }
    }

    // Transposed scatter epilogue: out[b][d][s] = C[s][d]
    #pragma unroll
    for (int mi = 0; mi < 2; ++mi) {
        #pragma unroll
        for (int ni = 0; ni < 4; ++ni) {
            size_t row = m0 + wm * 32 + mi * 16 + (lane >> 2);   // s
            size_t col = n0 + wn * 32 + ni * 8 + (lane & 3) * 2; // d
            float* o = Out + col * (size_t)S_ + row;
            o[0]              = c[mi][ni][0];
            o[(size_t)S_]     = c[mi][ni][1];
            o[8]              = c[mi][ni][2];
            o[(size_t)S_ + 8] = c[mi][ni][3];
        }
    }
}

// ---------------------------------------------------------------------------
// Elementwise kernels
// ---------------------------------------------------------------------------
__global__ void split3_kernel(const float4* __restrict__ in0,
                              const float4* __restrict__ in1,
                              const float4* __restrict__ in2,
                              ushort4* __restrict__ h0, ushort4* __restrict__ l0,
                              ushort4* __restrict__ h1, ushort4* __restrict__ l1,
                              ushort4* __restrict__ h2, ushort4* __restrict__ l2,
                              int n4) {
    int i = blockIdx.x * blockDim.x + threadIdx.x;
    if (i >= n4) return;
    int z = blockIdx.z;
    const float4* in = (z == 0) ? in0 : (z == 1) ? in1 : in2;
    ushort4* hi = (z == 0) ? h0 : (z == 1) ? h1 : h2;
    ushort4* lo = (z == 0) ? l0 : (z == 1) ? l1 : l2;
    float4 v = in[i];
    __nv_bfloat16 a0 = __float2bfloat16(v.x), a1 = __float2bfloat16(v.y);
    __nv_bfloat16 a2 = __float2bfloat16(v.z), a3 = __float2bfloat16(v.w);
    ushort4 H = { __bfloat16_as_ushort(a0), __bfloat16_as_ushort(a1),
                  __bfloat16_as_ushort(a2), __bfloat16_as_ushort(a3) };
    hi[i] = H;
    ushort4 L = { __bfloat16_as_ushort(__float2bfloat16(v.x - __bfloat162float(a0))),
                  __bfloat16_as_ushort(__float2bfloat16(v.y - __bfloat162float(a1))),
                  __bfloat16_as_ushort(__float2bfloat16(v.z - __bfloat162float(a2))),
                  __bfloat16_as_ushort(__float2bfloat16(v.w - __bfloat162float(a3))) };
    lo[i] = L;
}

// Transpose fp32 [R,C] -> bf16 hi/lo [C,R]  (per batch via blockIdx.z)
__global__ void transpose_split(const float* __restrict__ in,
                                bf16* __restrict__ ohi, bf16* __restrict__ olo,
                                int R, int C) {
    __shared__ float t[32][33];
    size_t base = (size_t)blockIdx.z * R * C;
    int c0 = blockIdx.x * 32, r0 = blockIdx.y * 32;
    int tx = threadIdx.x, ty = threadIdx.y;
    #pragma unroll
    for (int i = 0; i < 4; ++i)
        t[ty + 8 * i][tx] = in[base + (size_t)(r0 + ty + 8 * i) * C + c0 + tx];
    __syncthreads();
    #pragma unroll
    for (int i = 0; i < 4; ++i) {
        float v = t[tx][ty + 8 * i];
        bf16 h = __float2bfloat16(v);
        size_t o = base + (size_t)(c0 + ty + 8 * i) * R + r0 + tx;
        ohi[o] = h;
        olo[o] = __float2bfloat16(v - __bfloat162float(h));
    }
}

// ---------------------------------------------------------------------------
// Launch
// ---------------------------------------------------------------------------
extern "C" void kernel_launch(void* const* d_in, const int* in_sizes, int n_in,
                              void* d_out, int out_size) {
    const float* x    = (const float*)d_in[0];
    const float* w0   = (const float*)d_in[1];
    const float* w1   = (const float*)d_in[2];
    const float* wout = (const float*)d_in[3];
    float* out = (float*)d_out;

    void *xThi, *xTlo, *w0hi, *w0lo, *w1hi, *w1lo, *wohi, *wolo, *hhi, *hlo;
    cudaGetSymbolAddress(&xThi, g_xThi);
    cudaGetSymbolAddress(&xTlo, g_xTlo);
    cudaGetSymbolAddress(&w0hi, g_w0hi);
    cudaGetSymbolAddress(&w0lo, g_w0lo);
    cudaGetSymbolAddress(&w1hi, g_w1hi);
    cudaGetSymbolAddress(&w1lo, g_w1lo);
    cudaGetSymbolAddress(&wohi, g_wohi);
    cudaGetSymbolAddress(&wolo, g_wolo);
    cudaGetSymbolAddress(&hhi,  g_hhi);
    cudaGetSymbolAddress(&hlo,  g_hlo);

    cudaFuncSetAttribute(gemm1_fused, cudaFuncAttributeMaxDynamicSharedMemorySize, G1_SMEM);
    cudaFuncSetAttribute(gemm2_mma,   cudaFuncAttributeMaxDynamicSharedMemorySize, G2_SMEM);

    const int nW = F_ * D_;        // 67,108,864

    // 1) transpose+split x: [b][D][S] fp32 -> [b][S][D] bf16 hi/lo
    {
        dim3 blk(32, 8), grd(S_ / 32, D_ / 32, B_);
        transpose_split<<<grd, blk>>>(x, (bf16*)xThi, (bf16*)xTlo, D_, S_);
    }
    // 2) split all three weight matrices in one launch
    {
        dim3 grd(nW / 4 / 256, 1, 3);
        split3_kernel<<<grd, 256>>>(
            (const float4*)w0, (const float4*)w1, (const float4*)wout,
            (ushort4*)w0hi, (ushort4*)w0lo,
            (ushort4*)w1hi, (ushort4*)w1lo,
            (ushort4*)wohi, (ushort4*)wolo, nW / 4);
    }

    // 3) fused layer 1: H^T[S,F] = gelu(X^T W0^T) * (X^T W1^T), bf16 hi/lo
    {
        dim3 grd(S_ / 128, F_ / 64, B_);      // (16, 256, 2)
        gemm1_fused<<<grd, 256, G1_SMEM>>>(
            (const bf16*)xThi, (const bf16*)xTlo,
            (const bf16*)w0hi, (const bf16*)w0lo,
            (const bf16*)w1hi, (const bf16*)w1lo,
            (bf16*)hhi, (bf16*)hlo);
    }

    // 4) layer 2 + transposed epilogue: out[b][d][s] = (H^T Wout^T)[s][d]
    {
        dim3 grd(S_ / 128, D_ / 64, B_);      // (16, 64, 2)
        gemm2_mma<<<grd, 256, G2_SMEM>>>(
            (const bf16*)hhi, (const bf16*)hlo,
            (const bf16*)wohi, (const bf16*)wolo,
            out);
    }
}

// round 16
// speedup vs baseline: 1.0682x; 1.0682x over previous
#include <cuda_runtime.h>
#include <cuda_bf16.h>
#include <stdint.h>

typedef __nv_bfloat16 bf16;

// Problem dims (fixed)
#define B_ 2
#define D_ 4096
#define S_ 2048
#define F_ 16384

// ---------------------------------------------------------------------------
// Scratch (device globals; allocation-free per harness rules)
// ---------------------------------------------------------------------------
__device__ bf16  g_xThi[(size_t)B_ * S_ * D_];   // x^T per batch [S, D]
__device__ bf16  g_xTlo[(size_t)B_ * S_ * D_];
__device__ bf16  g_w0hi[(size_t)F_ * D_];
__device__ bf16  g_w0lo[(size_t)F_ * D_];
__device__ bf16  g_w1hi[(size_t)F_ * D_];
__device__ bf16  g_w1lo[(size_t)F_ * D_];
__device__ bf16  g_wohi[(size_t)D_ * F_];
__device__ bf16  g_wolo[(size_t)D_ * F_];
__device__ bf16  g_hhi[(size_t)B_ * S_ * F_];    // H^T  [S, F]
__device__ bf16  g_hlo[(size_t)B_ * S_ * F_];

// ---------------------------------------------------------------------------
// PTX helpers (sm_80-era only; NO tcgen05 — ptxas targets plain sm_103)
// ---------------------------------------------------------------------------
__device__ __forceinline__ void cp16(uint32_t s, const void* g) {
    asm volatile("cp.async.cg.shared.global [%0], [%1], 16;\n" :: "r"(s), "l"(g));
}

__device__ __forceinline__ void ldsm_x4(uint32_t addr, uint32_t* r) {
    asm volatile(
        "ldmatrix.sync.aligned.m8n8.x4.shared.b16 {%0,%1,%2,%3}, [%4];\n"
        : "=r"(r[0]), "=r"(r[1]), "=r"(r[2]), "=r"(r[3]) : "r"(addr));
}

__device__ __forceinline__ void mma_bf16(float* c, const uint32_t* a,
                                         uint32_t b0, uint32_t b1) {
    asm volatile(
        "mma.sync.aligned.m16n8k16.row.col.f32.bf16.bf16.f32 "
        "{%0,%1,%2,%3}, {%4,%5,%6,%7}, {%8,%9}, {%0,%1,%2,%3};\n"
        : "+f"(c[0]), "+f"(c[1]), "+f"(c[2]), "+f"(c[3])
        : "r"(a[0]), "r"(a[1]), "r"(a[2]), "r"(a[3]), "r"(b0), "r"(b1));
}

__device__ __forceinline__ float gelu_exact(float v) {
    return 0.5f * v * (1.0f + erff(v * 0.70710678118654752440f));
}

#define SWZ(x) ((x) ^ (((x) >> 3) & 0x70))

constexpr int BK = 64;

// ===========================================================================
// GEMM1 fused, 2 CTAs/SM (R14 config): CTA tile 128(S) x 32(F) PER PRODUCT;
// warps 0-3 compute gate = (xT)(w0^T), warps 4-7 compute up = (xT)(w1^T);
// warp tile 32x32. bf16x3, fp32 accum. 2-stage cp.async, BK=64, SW128.
// Stage: Ahi16K Alo16K W0h4K W0l4K W1h4K W1l4K = 48K; 2 stages = 96K.
// COOPERATIVE epilogue: both groups dump accums to smem; all 8 warps share
// the gelu/mul/split/store work (halved critical path vs R14).
// ===========================================================================
constexpr int G1_STAGE = 49152;
constexpr int G1_SMEM  = 2 * G1_STAGE;           // 98304

__device__ __forceinline__ void g1_load_stage(
    uint32_t st, const bf16* __restrict__ Ah, const bf16* __restrict__ Al,
    const bf16* __restrict__ W0h, const bf16* __restrict__ W0l,
    const bf16* __restrict__ W1h, const bf16* __restrict__ W1l,
    size_t m0, size_t n0, int k0, int tid) {
    const int K = D_;
    // A: 128 rows x 128B, hi+lo (1024 chunks each)
    #pragma unroll
    for (int i = 0; i < 4; ++i) {
        int cc = tid + i * 256;           // 0..1023
        int r = cc >> 3, cb = (cc & 7) * 16;
        size_t gbyte = (((m0 + r) * (size_t)K + k0) << 1) + cb;
        uint32_t s = SWZ((uint32_t)(r * 128 + cb));
        cp16(st + s,         (const char*)Ah + gbyte);
        cp16(st + 16384 + s, (const char*)Al + gbyte);
    }
    // B: 4 subtiles (w0h,w0l,w1h,w1l), each 32 rows x 128B = 256 chunks
    #pragma unroll
    for (int sub = 0; sub < 4; ++sub) {
        int cc = tid;                     // 0..255
        int r = cc >> 3, cb = (cc & 7) * 16;
        size_t gbyte = (((n0 + r) * (size_t)K + k0) << 1) + cb;
        uint32_t s = SWZ((uint32_t)(r * 128 + cb));
        const bf16* p = (sub == 0) ? W0h : (sub == 1) ? W0l : (sub == 2) ? W1h : W1l;
        cp16(st + 32768 + sub * 4096 + s, (const char*)p + gbyte);
    }
}

__global__ void __launch_bounds__(256, 2) gemm1_fused(
    const bf16* __restrict__ Ah, const bf16* __restrict__ Al,
    const bf16* __restrict__ W0h, const bf16* __restrict__ W0l,
    const bf16* __restrict__ W1h, const bf16* __restrict__ W1l,
    bf16* __restrict__ Hhi, bf16* __restrict__ Hlo) {
    extern __shared__ char smem[];
    uint32_t sb = (uint32_t)__cvta_generic_to_shared(smem);
    int tid = threadIdx.x, wid = tid >> 5, lane = tid & 31;
    int grp = wid >> 2;        // 0 = gate(w0), 1 = up(w1)
    int wg  = wid & 3;         // 4 warps along M, 32 rows each

    int b = blockIdx.z;
    const bf16* xh = Ah + (size_t)b * S_ * D_;
    const bf16* xl = Al + (size_t)b * S_ * D_;
    bf16* Oh = Hhi + (size_t)b * S_ * F_;
    bf16* Ol = Hlo + (size_t)b * S_ * F_;
    size_t m0 = (size_t)blockIdx.x * 128;
    size_t n0 = (size_t)blockIdx.y * 32;
    const int KT = D_ / BK;    // 64

    float c[2][4][4];
    #pragma unroll
    for (int mi = 0; mi < 2; ++mi)
        #pragma unroll
        for (int ni = 0; ni < 4; ++ni)
            #pragma unroll
            for (int r = 0; r < 4; ++r) c[mi][ni][r] = 0.0f;

    g1_load_stage(sb,            xh, xl, W0h, W0l, W1h, W1l, m0, n0, 0,  tid);
    asm volatile("cp.async.commit_group;\n" ::: "memory");
    g1_load_stage(sb + G1_STAGE, xh, xl, W0h, W0l, W1h, W1l, m0, n0, BK, tid);
    asm volatile("cp.async.commit_group;\n" ::: "memory");

    int aRow = wg * 32 + (lane & 15);
    int aCol = (lane >> 4) * 16;
    int bRow = (lane & 7) + ((lane >> 4) << 3);
    int bCol = ((lane >> 3) & 1) * 16;
    uint32_t bBase = 32768 + grp * 8192;    // this group's B (hi @+0, lo @+4096)

    for (int kt = 0; kt < KT; ++kt) {
        if (kt + 1 < KT) asm volatile("cp.async.wait_group 1;\n" ::: "memory");
        else             asm volatile("cp.async.wait_group 0;\n" ::: "memory");
        __syncthreads();
        uint32_t st = sb + (kt & 1) * G1_STAGE;

        #pragma unroll
        for (int ks = 0; ks < 4; ++ks) {
            uint32_t ah[2][4], al[2][4], bh[2][4], bl[2][4];
            #pragma unroll
            for (int mi = 0; mi < 2; ++mi) {
                uint32_t off = SWZ((uint32_t)((aRow + mi * 16) * 128 + ks * 32 + aCol));
                ldsm_x4(st + off,         ah[mi]);
                ldsm_x4(st + 16384 + off, al[mi]);
            }
            #pragma unroll
            for (int nj = 0; nj < 2; ++nj) {
                uint32_t off = SWZ((uint32_t)((bRow + nj * 16) * 128 + ks * 32 + bCol));
                ldsm_x4(st + bBase + off,        bh[nj]);
                ldsm_x4(st + bBase + 4096 + off, bl[nj]);
            }
            #pragma unroll
            for (int mi = 0; mi < 2; ++mi)
                #pragma unroll
                for (int ni = 0; ni < 4; ++ni) {
                    int nj = ni >> 1, pr = (ni & 1) * 2;
                    mma_bf16(c[mi][ni], ah[mi], bh[nj][pr], bh[nj][pr + 1]);
                }
            #pragma unroll
            for (int mi = 0; mi < 2; ++mi)
                #pragma unroll
                for (int ni = 0; ni < 4; ++ni) {
                    int nj = ni >> 1, pr = (ni & 1) * 2;
                    mma_bf16(c[mi][ni], ah[mi], bl[nj][pr], bl[nj][pr + 1]);
                }
            #pragma unroll
            for (int mi = 0; mi < 2; ++mi)
                #pragma unroll
                for (int ni = 0; ni < 4; ++ni) {
                    int nj = ni >> 1, pr = (ni & 1) * 2;
                    mma_bf16(c[mi][ni], al[mi], bh[nj][pr], bh[nj][pr + 1]);
                }
        }
        __syncthreads();   // stage fully consumed; safe to refill below
        if (kt + 2 < KT) {
            g1_load_stage(st, xh, xl, W0h, W0l, W1h, W1l, m0, n0, (kt + 2) * BK, tid);
            asm volatile("cp.async.commit_group;\n" ::: "memory");
        }
    }

    // ---- Cooperative fused epilogue: h = gelu(gate) * up, bf16 hi/lo ----
    // Both groups dump fp32 accums to smem (gate @ +0, up @ +16KB), then all
    // 8 warps each process 16 of the 32 slots (warp w -> wg=w&3, mi=w>>2).
    // fp32 smem round-trip is bit-exact: numerics identical to R14.
    float* gsm = (float*)smem;               // 2 x (4 warps x 1024 floats)
    {
        float* dst = gsm + grp * 4096;
        int slotBase = wg * 1024 + lane;     // lane-major: conflict-free
        #pragma unroll
        for (int mi = 0; mi < 2; ++mi)
            #pragma unroll
            for (int ni = 0; ni < 4; ++ni)
                #pragma unroll
                for (int r = 0; r < 4; ++r)
                    dst[slotBase + (mi * 16 + ni * 4 + r) * 32] = c[mi][ni][r];
    }
    __syncthreads();
    {
        int wg_src = wid & 3;
        int mi_src = wid >> 2;               // each warp: one (wg, mi) pair
        int base = wg_src * 1024 + lane + mi_src * 16 * 32;
        size_t row = m0 + wg_src * 32 + mi_src * 16 + (lane >> 2);
        size_t col0 = n0 + (lane & 3) * 2;
        #pragma unroll
        for (int ni = 0; ni < 4; ++ni) {
            float h[4];
            #pragma unroll
            for (int r = 0; r < 4; ++r) {
                int sl = base + (ni * 4 + r) * 32;
                h[r] = gelu_exact(gsm[sl]) * gsm[4096 + sl];
            }
            size_t col = col0 + ni * 8;
            #pragma unroll
            for (int half = 0; half < 2; ++half) {
                float v0 = h[half * 2], v1 = h[half * 2 + 1];
                bf16 h0 = __float2bfloat16(v0), h1 = __float2bfloat16(v1);
                __nv_bfloat162 hi2 = { h0, h1 };
                __nv_bfloat162 lo2 = { __float2bfloat16(v0 - __bfloat162float(h0)),
                                       __float2bfloat16(v1 - __bfloat162float(h1)) };
                size_t o = (row + half * 8) * (size_t)F_ + col;
                *(__nv_bfloat162*)(Oh + o) = hi2;
                *(__nv_bfloat162*)(Ol + o) = lo2;
            }
        }
    }
}

// ===========================================================================
// GEMM2, 2 CTAs/SM (unchanged from R14): CTA 128(S) x 64(D), 8 warps as
// 4(M) x 2(N), warp tile 32x32. 2-stage cp.async, BK=64, SW128.
// Writes out[b][d][s] directly (transposed scatter).
// ===========================================================================
constexpr int G2_STAGE = 49152;
constexpr int G2_SMEM  = 2 * G2_STAGE;      // 98304

__device__ __forceinline__ void g2_load_stage(
    uint32_t st, const bf16* __restrict__ Ah, const bf16* __restrict__ Al,
    const bf16* __restrict__ Bh, const bf16* __restrict__ Bl,
    size_t m0, size_t n0, int k0, int K, int tid) {
    #pragma unroll
    for (int i = 0; i < 4; ++i) {
        int cc = tid + i * 256;
        int r = cc >> 3, cb = (cc & 7) * 16;
        size_t gbyte = (((m0 + r) * (size_t)K + k0) << 1) + cb;
        uint32_t s = SWZ((uint32_t)(r * 128 + cb));
        cp16(st + s,         (const char*)Ah + gbyte);
        cp16(st + 16384 + s, (const char*)Al + gbyte);
    }
    #pragma unroll
    for (int i = 0; i < 2; ++i) {
        int cc = tid + i * 256;
        int r = cc >> 3, cb = (cc & 7) * 16;
        size_t gbyte = (((n0 + r) * (size_t)K + k0) << 1) + cb;
        uint32_t s = SWZ((uint32_t)(r * 128 + cb));
        cp16(st + 32768 + s, (const char*)Bh + gbyte);
        cp16(st + 40960 + s, (const char*)Bl + gbyte);
    }
}

__global__ void __launch_bounds__(256, 2) gemm2_mma(
    const bf16* __restrict__ gAh, const bf16* __restrict__ gAl,
    const bf16* __restrict__ Bh, const bf16* __restrict__ Bl,
    float* __restrict__ gOut) {
    extern __shared__ char smem[];
    uint32_t sb = (uint32_t)__cvta_generic_to_shared(smem);
    int tid = threadIdx.x, wid = tid >> 5, lane = tid & 31;
    int wm = wid >> 1;        // 4 warps along M(S), 32 rows each
    int wn = wid & 1;         // 2 warps along N(D), 32 cols each

    int b = blockIdx.z;
    const bf16* Ah = gAh + (size_t)b * S_ * F_;
    const bf16* Al = gAl + (size_t)b * S_ * F_;
    float* Out = gOut + (size_t)b * D_ * S_;
    size_t m0 = (size_t)blockIdx.x * 128;
    size_t n0 = (size_t)blockIdx.y * 64;
    const int K = F_;
    const int KT = K / BK;    // 256

    float c[2][4][4];
    #pragma unroll
    for (int mi = 0; mi < 2; ++mi)
        #pragma unroll
        for (int ni = 0; ni < 4; ++ni)
            #pragma unroll
            for (int r = 0; r < 4; ++r) c[mi][ni][r] = 0.0f;

    g2_load_stage(sb,            Ah, Al, Bh, Bl, m0, n0, 0,  K, tid);
    asm volatile("cp.async.commit_group;\n" ::: "memory");
    g2_load_stage(sb + G2_STAGE, Ah, Al, Bh, Bl, m0, n0, BK, K, tid);
    asm volatile("cp.async.commit_group;\n" ::: "memory");

    int aRow = wm * 32 + (lane & 15);
    int aCol = (lane >> 4) * 16;
    int bRow = wn * 32 + (lane & 7) + ((lane >> 4) << 3);
    int bCol = ((lane >> 3) & 1) * 16;

    for (int kt = 0; kt < KT; ++kt) {
        if (kt + 1 < KT) asm volatile("cp.async.wait_group 1;\n" ::: "memory");
        else             asm volatile("cp.async.wait_group 0;\n" ::: "memory");
        __syncthreads();
        uint32_t st = sb + (kt & 1) * G2_STAGE;

        #pragma unroll
        for (int ks = 0; ks < 4; ++ks) {
            uint32_t ah[2][4], al[2][4], bh[2][4], bl[2][4];
            #pragma unroll
            for (int mi = 0; mi < 2; ++mi) {
                uint32_t off = SWZ((uint32_t)((aRow + mi * 16) * 128 + ks * 32 + aCol));
                ldsm_x4(st + off,         ah[mi]);
                ldsm_x4(st + 16384 + off, al[mi]);
            }
            #pragma unroll
            for (int nj = 0; nj < 2; ++nj) {
                uint32_t off = SWZ((uint32_t)((bRow + nj * 16) * 128 + ks * 32 + bCol));
                ldsm_x4(st + 32768 + off, bh[nj]);
                ldsm_x4(st + 40960 + off, bl[nj]);
            }
            #pragma unroll
            for (int mi = 0; mi < 2; ++mi)
                #pragma unroll
                for (int ni = 0; ni < 4; ++ni) {
                    int nj = ni >> 1, pr = (ni & 1) * 2;
                    mma_bf16(c[mi][ni], ah[mi], bh[nj][pr], bh[nj][pr + 1]);
                }
            #pragma unroll
            for (int mi = 0; mi < 2; ++mi)
                #pragma unroll
                for (int ni = 0; ni < 4; ++ni) {
                    int nj = ni >> 1, pr = (ni & 1) * 2;
                    mma_bf16(c[mi][ni], ah[mi], bl[nj][pr], bl[nj][pr + 1]);
                }
            #pragma unroll
            for (int mi = 0; mi < 2; ++mi)
                #pragma unroll
                for (int ni = 0; ni < 4; ++ni) {
                    int nj = ni >> 1, pr = (ni & 1) * 2;
                    mma_bf16(c[mi][ni], al[mi], bh[nj][pr], bh[nj][pr + 1]);
                }
        }
        __syncthreads();
        if (kt + 2 < KT) {
            g2_load_stage(st, Ah, Al, Bh, Bl, m0, n0, (kt + 2) * BK, K, tid);
            asm volatile("cp.async.commit_group;\n" ::: "memory");
        }
    }

    // Transposed scatter epilogue: out[b][d][s] = C[s][d]
    #pragma unroll
    for (int mi = 0; mi < 2; ++mi) {
        #pragma unroll
        for (int ni = 0; ni < 4; ++ni) {
            size_t row = m0 + wm * 32 + mi * 16 + (lane >> 2);   // s
            size_t col = n0 + wn * 32 + ni * 8 + (lane & 3) * 2; // d
            float* o = Out + col * (size_t)S_ + row;
            o[0]              = c[mi][ni][0];
            o[(size_t)S_]     = c[mi][ni][1];
            o[8]              = c[mi][ni][2];
            o[(size_t)S_ + 8] = c[mi][ni][3];
        }
    }
}

// ---------------------------------------------------------------------------
// Elementwise kernels
// ---------------------------------------------------------------------------
__global__ void split3_kernel(const float4* __restrict__ in0,
                              const float4* __restrict__ in1,
                              const float4* __restrict__ in2,
                              ushort4* __restrict__ h0, ushort4* __restrict__ l0,
                              ushort4* __restrict__ h1, ushort4* __restrict__ l1,
                              ushort4* __restrict__ h2, ushort4* __restrict__ l2,
                              int n4) {
    int i = blockIdx.x * blockDim.x + threadIdx.x;
    if (i >= n4) return;
    int z = blockIdx.z;
    const float4* in = (z == 0) ? in0 : (z == 1) ? in1 : in2;
    ushort4* hi = (z == 0) ? h0 : (z == 1) ? h1 : h2;
    ushort4* lo = (z == 0) ? l0 : (z == 1) ? l1 : l2;
    float4 v = in[i];
    __nv_bfloat16 a0 = __float2bfloat16(v.x), a1 = __float2bfloat16(v.y);
    __nv_bfloat16 a2 = __float2bfloat16(v.z), a3 = __float2bfloat16(v.w);
    ushort4 H = { __bfloat16_as_ushort(a0), __bfloat16_as_ushort(a1),
                  __bfloat16_as_ushort(a2), __bfloat16_as_ushort(a3) };
    hi[i] = H;
    ushort4 L = { __bfloat16_as_ushort(__float2bfloat16(v.x - __bfloat162float(a0))),
                  __bfloat16_as_ushort(__float2bfloat16(v.y - __bfloat162float(a1))),
                  __bfloat16_as_ushort(__float2bfloat16(v.z - __bfloat162float(a2))),
                  __bfloat16_as_ushort(__float2bfloat16(v.w - __bfloat162float(a3))) };
    lo[i] = L;
}

// Transpose fp32 [R,C] -> bf16 hi/lo [C,R]  (per batch via blockIdx.z)
__global__ void transpose_split(const float* __restrict__ in,
                                bf16* __restrict__ ohi, bf16* __restrict__ olo,
                                int R, int C) {
    __shared__ float t[32][33];
    size_t base = (size_t)blockIdx.z * R * C;
    int c0 = blockIdx.x * 32, r0 = blockIdx.y * 32;
    int tx = threadIdx.x, ty = threadIdx.y;
    #pragma unroll
    for (int i = 0; i < 4; ++i)
        t[ty + 8 * i][tx] = in[base + (size_t)(r0 + ty + 8 * i) * C + c0 + tx];
    __syncthreads();
    #pragma unroll
    for (int i = 0; i < 4; ++i) {
        float v = t[tx][ty + 8 * i];
        bf16 h = __float2bfloat16(v);
        size_t o = base + (size_t)(c0 + ty + 8 * i) * R + r0 + tx;
        ohi[o] = h;
        olo[o] = __float2bfloat16(v - __bfloat162float(h));
    }
}

// ---------------------------------------------------------------------------
// Launch
// ---------------------------------------------------------------------------
extern "C" void kernel_launch(void* const* d_in, const int* in_sizes, int n_in,
                              void* d_out, int out_size) {
    const float* x    = (const float*)d_in[0];
    const float* w0   = (const float*)d_in[1];
    const float* w1   = (const float*)d_in[2];
    const float* wout = (const float*)d_in[3];
    float* out = (float*)d_out;

    void *xThi, *xTlo, *w0hi, *w0lo, *w1hi, *w1lo, *wohi, *wolo, *hhi, *hlo;
    cudaGetSymbolAddress(&xThi, g_xThi);
    cudaGetSymbolAddress(&xTlo, g_xTlo);
    cudaGetSymbolAddress(&w0hi, g_w0hi);
    cudaGetSymbolAddress(&w0lo, g_w0lo);
    cudaGetSymbolAddress(&w1hi, g_w1hi);
    cudaGetSymbolAddress(&w1lo, g_w1lo);
    cudaGetSymbolAddress(&wohi, g_wohi);
    cudaGetSymbolAddress(&wolo, g_wolo);
    cudaGetSymbolAddress(&hhi,  g_hhi);
    cudaGetSymbolAddress(&hlo,  g_hlo);

    cudaFuncSetAttribute(gemm1_fused, cudaFuncAttributeMaxDynamicSharedMemorySize, G1_SMEM);
    cudaFuncSetAttribute(gemm2_mma,   cudaFuncAttributeMaxDynamicSharedMemorySize, G2_SMEM);

    const int nW = F_ * D_;        // 67,108,864

    // 1) transpose+split x: [b][D][S] fp32 -> [b][S][D] bf16 hi/lo
    {
        dim3 blk(32, 8), grd(S_ / 32, D_ / 32, B_);
        transpose_split<<<grd, blk>>>(x, (bf16*)xThi, (bf16*)xTlo, D_, S_);
    }
    // 2) split all three weight matrices in one launch
    {
        dim3 grd(nW / 4 / 256, 1, 3);
        split3_kernel<<<grd, 256>>>(
            (const float4*)w0, (const float4*)w1, (const float4*)wout,
            (ushort4*)w0hi, (ushort4*)w0lo,
            (ushort4*)w1hi, (ushort4*)w1lo,
            (ushort4*)wohi, (ushort4*)wolo, nW / 4);
    }

    // 3) fused layer 1: H^T[S,F] = gelu(X^T W0^T) * (X^T W1^T), bf16 hi/lo
    {
        dim3 grd(S_ / 128, F_ / 32, B_);      // (16, 512, 2)
        gemm1_fused<<<grd, 256, G1_SMEM>>>(
            (const bf16*)xThi, (const bf16*)xTlo,
            (const bf16*)w0hi, (const bf16*)w0lo,
            (const bf16*)w1hi, (const bf16*)w1lo,
            (bf16*)hhi, (bf16*)hlo);
    }

    // 4) layer 2 + transposed epilogue: out[b][d][s] = (H^T Wout^T)[s][d]
    {
        dim3 grd(S_ / 128, D_ / 64, B_);      // (16, 64, 2)
        gemm2_mma<<<grd, 256, G2_SMEM>>>(
            (const bf16*)hhi, (const bf16*)hlo,
            (const bf16*)wohi, (const bf16*)wolo,
            out);
    }
}